// round 11
// baseline (speedup 1.0000x reference)
#include <cuda_runtime.h>
#include <cuda_bf16.h>
#include <cstdint>

#define DIMN 512
#define MT   64
#define NROWS 65536
#define NCTAS (NROWS / MT)        // 1024
#define NTHREADS 512
#define ETA   0.1f
#define OMETA 0.9f
#define NCH_TOTAL (9 * 16)        // 144 chunks of 32 k-rows

// SMEM: A-tile 64KB + pair-private B rings (8 pairs x 4 slots x 4KB = 128KB) + flags
static constexpr uint32_t A_OFF  = 0;
static constexpr uint32_t PB_OFF = 65536;
static constexpr uint32_t FL_OFF = 196608;        // flags[2][16] = 128B
static constexpr uint32_t SMEM_TOTAL = 196736;

// G' = -eta*0.5*(G+G^T), diag 0, bf16, pre-swizzled per (chunk rb, pair p) 4KB slice:
// slice = k rows rb*32..+31, n cols p*64..+63, image addr within slice:
//   rr*128 + ((cu ^ (rr&7))<<4) + (nl&7)*2,  rr=k&31, nl=n&63, cu=nl>>3
__device__ unsigned char g_blob[16 * 8 * 4096];   // 512KB

__global__ void lca_prep_kernel(const float* __restrict__ G) {
    int idx = blockIdx.x * blockDim.x + threadIdx.x;   // 262144
    int k = idx >> 9, n = idx & 511;
    float v = (k == n) ? 0.0f : -ETA * 0.5f * (G[k * DIMN + n] + G[n * DIMN + k]);
    __nv_bfloat16 h = __float2bfloat16(v);
    int rr = k & 31, nl = n & 63, cu = nl >> 3;
    uint32_t dst = ((uint32_t)(k >> 5) * 8u + (uint32_t)(n >> 6)) * 4096u
                 + (uint32_t)rr * 128u + ((uint32_t)(cu ^ (rr & 7)) << 4) + (uint32_t)(nl & 7) * 2u;
    *reinterpret_cast<unsigned short*>(g_blob + dst) = *reinterpret_cast<unsigned short*>(&h);
}

__device__ __forceinline__ uint32_t smem_u32(const void* p) {
    uint32_t a;
    asm("{ .reg .u64 t; cvta.to.shared.u64 t, %1; cvt.u32.u64 %0, t; }" : "=r"(a) : "l"(p));
    return a;
}
__device__ __forceinline__ void ldsm4(uint32_t* r, uint32_t addr) {
    asm volatile("ldmatrix.sync.aligned.m8n8.x4.shared.b16 {%0,%1,%2,%3}, [%4];"
                 : "=r"(r[0]), "=r"(r[1]), "=r"(r[2]), "=r"(r[3]) : "r"(addr));
}
__device__ __forceinline__ void ldsm4t(uint32_t* r, uint32_t addr) {
    asm volatile("ldmatrix.sync.aligned.m8n8.x4.trans.shared.b16 {%0,%1,%2,%3}, [%4];"
                 : "=r"(r[0]), "=r"(r[1]), "=r"(r[2]), "=r"(r[3]) : "r"(addr));
}
__device__ __forceinline__ void mma_bf16(float* c, const uint32_t* a, uint32_t b0, uint32_t b1) {
    asm volatile("mma.sync.aligned.m16n8k16.row.col.f32.bf16.bf16.f32 "
                 "{%0,%1,%2,%3}, {%4,%5,%6,%7}, {%8,%9}, {%0,%1,%2,%3};"
                 : "+f"(c[0]), "+f"(c[1]), "+f"(c[2]), "+f"(c[3])
                 : "r"(a[0]), "r"(a[1]), "r"(a[2]), "r"(a[3]), "r"(b0), "r"(b1));
}
__device__ __forceinline__ void cp_async16(uint32_t dst, const void* src) {
    asm volatile("cp.async.cg.shared.global [%0], [%1], 16;" :: "r"(dst), "l"(src) : "memory");
}
#define COMMIT() asm volatile("cp.async.commit_group;" ::: "memory")
#define WAITG(n) asm volatile("cp.async.wait_group %0;" :: "n"(n) : "memory")

__global__ __launch_bounds__(NTHREADS, 1)
void lca_main_kernel(const float* __restrict__ u,
                     const float* __restrict__ log_lam,
                     float* __restrict__ out) {
    extern __shared__ char smem[];
    const uint32_t sb = smem_u32(smem);
    volatile uint32_t* flagsm = reinterpret_cast<volatile uint32_t*>(smem + FL_OFF); // [2][16]
    const int tid  = threadIdx.x;
    const int lane = tid & 31;
    const int warp = tid >> 5;
    const int wm = warp >> 3;              // 0..1 (m half)
    const int wn = warp & 7;               // 0..7 (pair id / 64-col group)
    const int m0 = wm * 32;
    const int n0 = wn * 64;
    const int tpair = wm * 32 + lane;      // 0..63 within pair
    const int barid = 1 + wn;              // named barrier per pair
    const int grow0 = blockIdx.x * MT;
    const float lam = expf(log_lam[0]);
    const int r4 = lane >> 2;
    const int c2 = (lane & 3) * 2;

    float acc[2][8][4];

    // A-operand ldsm addressing (unchanged from the proven R4 kernel)
    const uint32_t a_lrow0 = sb + A_OFF + (uint32_t)(m0 + (lane & 15)) * 1024u;
    const uint32_t a_lrow1 = a_lrow0 + 16u * 1024u;
    const uint32_t a_cbs = ((uint32_t)(lane >> 4)) ^ ((uint32_t)(lane & 7));
    // B-operand (pair-private 4KB slice, 128B rows): row = h*16 + (lane&15)
    const uint32_t b_rowoff = (uint32_t)(lane & 15) * 128u;
    uint32_t b_pu[4];
#pragma unroll
    for (int p = 0; p < 4; p++)
        b_pu[p] = ((((uint32_t)(2 * p) + (uint32_t)(lane >> 4)) ^ (uint32_t)(lane & 7)) << 4);
    const uint32_t pb_base = sb + PB_OFF + (uint32_t)wn * 16384u;

    // issue this thread's 64B of (chunk rb, this pair) into ring slot s  (caller commits)
    auto issue_slice = [&](int rb, uint32_t s) {
        const char* src = (const char*)g_blob + ((size_t)rb * 8 + (size_t)wn) * 4096 + (size_t)tpair * 64;
        uint32_t dst = pb_base + s * 4096u + (uint32_t)tpair * 64u;
#pragma unroll
        for (int j = 0; j < 4; j++) cp_async16(dst + (uint32_t)j * 16u, src + j * 16);
    };
    auto flag_of = [&](int kb) -> uint32_t { return flagsm[kb] | flagsm[16 + kb]; };

    // ---- init: v1 = eta*u; a1 = soft(v1) -> SMEM + flags; acc = 0.9*v1 + 0.1*u ----
    {
        bool nzlo = false, nzhi = false;
#pragma unroll
        for (int fm = 0; fm < 2; fm++)
#pragma unroll
        for (int rh = 0; rh < 2; rh++) {
            int rl = m0 + fm * 16 + rh * 8 + r4;
            const float* urow = u + (size_t)(grow0 + rl) * DIMN;
            uint32_t abase = sb + A_OFF + (uint32_t)rl * 1024u + (uint32_t)(c2 * 2);
            uint32_t sw = (uint32_t)(rl & 7);
#pragma unroll
            for (int ni = 0; ni < 8; ni++) {
                float2 uv = *(const float2*)(urow + n0 + ni * 8 + c2);
                float v0 = ETA * uv.x, v1 = ETA * uv.y;
                float s0 = fabsf(v0) - lam, s1 = fabsf(v1) - lam;
                float a0 = (s0 > 0.0f) ? copysignf(s0, v0) : 0.0f;
                float a1 = (s1 > 0.0f) ? copysignf(s1, v1) : 0.0f;
                bool nz = (a0 != 0.0f) || (a1 != 0.0f);
                if (ni < 4) nzlo |= nz; else nzhi |= nz;
                __nv_bfloat162 h2 = __floats2bfloat162_rn(a0, a1);
                uint32_t unit = (uint32_t)(wn * 8 + ni);
                uint32_t aaddr = abase + ((unit ^ sw) << 4);
                asm volatile("st.shared.b32 [%0], %1;" :: "r"(aaddr), "r"(*(uint32_t*)&h2) : "memory");
                acc[fm][ni][rh * 2 + 0] = fmaf(OMETA, v0, ETA * uv.x);
                acc[fm][ni][rh * 2 + 1] = fmaf(OMETA, v1, ETA * uv.y);
            }
        }
        bool wlo = __any_sync(0xFFFFFFFFu, nzlo);
        bool whi = __any_sync(0xFFFFFFFFu, nzhi);
        if (lane == 0) {
            flagsm[wm * 16 + 2 * wn + 0] = wlo ? 1u : 0u;
            flagsm[wm * 16 + 2 * wn + 1] = whi ? 1u : 0u;
        }
    }
    __syncthreads();   // A-tile + flags visible

    // prologue: chunks 0,1 into slots 0,1 (conditional on flags; commit always)
    if (flag_of(0)) issue_slice(0, 0u);
    COMMIT();
    if (flag_of(1)) issue_slice(1, 1u);
    COMMIT();

    // ---- 9 iterations x 16 chunks; only pair-local sync inside ----
#pragma unroll 1
    for (int it = 0; it < 9; it++) {
#pragma unroll 1
        for (int kb = 0; kb < 16; kb++) {
            const int c = it * 16 + kb;
            // issue chunk c+2 into slot (c+2)&3; commit unconditionally
            {
                const int cp2 = c + 2;
                if (cp2 < NCH_TOTAL) {
                    bool ld = (kb < 14) ? (flag_of(kb + 2) != 0u) : true;
                    if (ld) issue_slice(cp2 & 15, (uint32_t)(cp2 & 3));
                }
                COMMIT();
            }
            WAITG(2);                                  // own loads of chunk c landed
            asm volatile("bar.sync %0, 64;" :: "r"(barid) : "memory");  // pair sync

            if (flag_of(kb)) {
                const uint32_t bb = pb_base + (uint32_t)(c & 3) * 4096u + b_rowoff;
                uint32_t Af[2][8], Bf[2][16];
                {   // preload k16 step 0 (A cu = kb*4)
                    uint32_t aoff = (((uint32_t)(kb << 2) ^ a_cbs) << 4);
                    ldsm4(&Af[0][0], a_lrow0 + aoff);
                    ldsm4(&Af[0][4], a_lrow1 + aoff);
#pragma unroll
                    for (int p = 0; p < 4; p++) ldsm4t(&Bf[0][4 * p], bb + b_pu[p]);
                }
#pragma unroll
                for (int h = 0; h < 2; h++) {
                    const int cur = h & 1, nxt = cur ^ 1;
                    if (h < 1) {   // preload step 1 (A cu = kb*4+2; B rows +16)
                        uint32_t aoff = ((((uint32_t)(kb << 2)) | 2u) ^ a_cbs) << 4;
                        ldsm4(&Af[nxt][0], a_lrow0 + aoff);
                        ldsm4(&Af[nxt][4], a_lrow1 + aoff);
#pragma unroll
                        for (int p = 0; p < 4; p++) ldsm4t(&Bf[nxt][4 * p], bb + 2048u + b_pu[p]);
                    }
#pragma unroll
                    for (int p = 0; p < 4; p++) {
                        mma_bf16(acc[0][2 * p + 0], &Af[cur][0], Bf[cur][4 * p + 0], Bf[cur][4 * p + 1]);
                        mma_bf16(acc[0][2 * p + 1], &Af[cur][0], Bf[cur][4 * p + 2], Bf[cur][4 * p + 3]);
                        mma_bf16(acc[1][2 * p + 0], &Af[cur][4], Bf[cur][4 * p + 0], Bf[cur][4 * p + 1]);
                        mma_bf16(acc[1][2 * p + 1], &Af[cur][4], Bf[cur][4 * p + 2], Bf[cur][4 * p + 3]);
                    }
                }
            }
        }
        __syncthreads();   // all pairs done with A-tile before rewrite

        if (it < 8) {
            bool nzlo = false, nzhi = false;
#pragma unroll
            for (int fm = 0; fm < 2; fm++)
#pragma unroll
            for (int rh = 0; rh < 2; rh++) {
                int rl = m0 + fm * 16 + rh * 8 + r4;
                const float* urow = u + (size_t)(grow0 + rl) * DIMN;
                uint32_t abase = sb + A_OFF + (uint32_t)rl * 1024u + (uint32_t)(c2 * 2);
                uint32_t sw = (uint32_t)(rl & 7);
#pragma unroll
                for (int ni = 0; ni < 8; ni++) {
                    float v0 = acc[fm][ni][rh * 2 + 0];
                    float v1 = acc[fm][ni][rh * 2 + 1];
                    float s0 = fabsf(v0) - lam, s1 = fabsf(v1) - lam;
                    float a0 = (s0 > 0.0f) ? copysignf(s0, v0) : 0.0f;
                    float a1 = (s1 > 0.0f) ? copysignf(s1, v1) : 0.0f;
                    bool nz = (a0 != 0.0f) || (a1 != 0.0f);
                    if (ni < 4) nzlo |= nz; else nzhi |= nz;
                    __nv_bfloat162 h2 = __floats2bfloat162_rn(a0, a1);
                    uint32_t unit = (uint32_t)(wn * 8 + ni);
                    uint32_t aaddr = abase + ((unit ^ sw) << 4);
                    asm volatile("st.shared.b32 [%0], %1;" :: "r"(aaddr), "r"(*(uint32_t*)&h2) : "memory");
                    float2 uv = *(const float2*)(urow + n0 + ni * 8 + c2);
                    acc[fm][ni][rh * 2 + 0] = fmaf(OMETA, v0, ETA * uv.x);
                    acc[fm][ni][rh * 2 + 1] = fmaf(OMETA, v1, ETA * uv.y);
                }
            }
            bool wlo = __any_sync(0xFFFFFFFFu, nzlo);
            bool whi = __any_sync(0xFFFFFFFFu, nzhi);
            if (lane == 0) {
                flagsm[wm * 16 + 2 * wn + 0] = wlo ? 1u : 0u;
                flagsm[wm * 16 + 2 * wn + 1] = whi ? 1u : 0u;
            }
            __syncthreads();   // a_{t+1} + flags visible before next iteration
        } else {
            // final: a10 = soft(v10) -> out
#pragma unroll
            for (int fm = 0; fm < 2; fm++)
#pragma unroll
            for (int rh = 0; rh < 2; rh++) {
                int rl = m0 + fm * 16 + rh * 8 + r4;
                float* orow = out + (size_t)(grow0 + rl) * DIMN;
#pragma unroll
                for (int ni = 0; ni < 8; ni++) {
                    float v0 = acc[fm][ni][rh * 2 + 0];
                    float v1 = acc[fm][ni][rh * 2 + 1];
                    float s0 = fabsf(v0) - lam, s1 = fabsf(v1) - lam;
                    float2 o;
                    o.x = (s0 > 0.0f) ? copysignf(s0, v0) : 0.0f;
                    o.y = (s1 > 0.0f) ? copysignf(s1, v1) : 0.0f;
                    *(float2*)(orow + n0 + ni * 8 + c2) = o;
                }
            }
        }
    }
}

extern "C" void kernel_launch(void* const* d_in, const int* in_sizes, int n_in,
                              void* d_out, int out_size) {
    const float* u = nullptr;
    const float* G = nullptr;
    const float* ll = nullptr;
    for (int i = 0; i < n_in; i++) {
        if (in_sizes[i] == NROWS * DIMN)      u  = (const float*)d_in[i];
        else if (in_sizes[i] == DIMN * DIMN)  G  = (const float*)d_in[i];
        else                                  ll = (const float*)d_in[i];
    }
    float* out = (float*)d_out;

    lca_prep_kernel<<<512, 512>>>(G);

    cudaFuncSetAttribute(lca_main_kernel,
                         cudaFuncAttributeMaxDynamicSharedMemorySize, SMEM_TOTAL);
    lca_main_kernel<<<NCTAS, NTHREADS, SMEM_TOTAL>>>(u, ll, out);
}